// round 12
// baseline (speedup 1.0000x reference)
#include <cuda_runtime.h>
#include <cuda_bf16.h>
#include <cfloat>
#include <cstdint>

// Problem constants
#define BATCH 8
#define NT 1024
#define CH 512
#define NBOX 256
#define OS 7
#define KDIM (OS * OS * CH)      // 25088; K order: c*49 + (i*7+j) (NATIVE conv_w order)
#define XELEMS (BATCH * NT * CH) // 4194304
#define OUTFEATS (NBOX * CH)     // 131072
#define WELEMS (CH * KDIM)       // 12845056

// GEMM config (mma.sync path — base sm_103 target has NO tcgen05)
#define GM 128
#define GN 128
#define SPLITS 16
#define KCHUNK (KDIM / SPLITS)   // 1568
#define KST 32
#define NST (KCHUNK / KST)       // 49

// smem: per stage 4 tiles (Ahi,Alo,Bhi,Blo), 128 rows x 32 bf16, row padded
// to 80B (64B data + 16B pad): r*80 mod 128 covers 8 distinct 16B bank
// groups -> ldmatrix conflict-free, and 80 is a multiple of 16 for cp.async.
#define RS_BYTES 80
#define TILE_BYTES (128 * RS_BYTES)      // 10240
#define OFF_AHI 0
#define OFF_ALO (TILE_BYTES)
#define OFF_BHI (2 * TILE_BYTES)
#define OFF_BLO (3 * TILE_BYTES)
#define STAGE_BYTES (4 * TILE_BYTES)     // 40960
#define NBUF 3
#define GEMM_SMEM (NBUF * STAGE_BYTES)   // 122880

// Device scratch (allocation-free rule: __device__ globals)
__device__ __align__(16) __nv_bfloat16 g_Ahi[NBOX * KDIM];
__device__ __align__(16) __nv_bfloat16 g_Alo[NBOX * KDIM];
__device__ __align__(16) __nv_bfloat16 g_Bhi[WELEMS];
__device__ __align__(16) __nv_bfloat16 g_Blo[WELEMS];
__device__ __align__(16) float g_partial[SPLITS * OUTFEATS];

// ---------------------------------------------------------------------------
// helpers
// ---------------------------------------------------------------------------
__device__ __forceinline__ uint32_t smem_to_u32(const void* p) {
    uint32_t a;
    asm("{ .reg .u64 t; cvta.to.shared.u64 t, %1; cvt.u32.u64 %0, t; }" : "=r"(a) : "l"(p));
    return a;
}
__device__ __forceinline__ void ldsm_x4(uint32_t* r, uint32_t addr) {
    asm volatile("ldmatrix.sync.aligned.m8n8.x4.shared.b16 {%0,%1,%2,%3}, [%4];"
        : "=r"(r[0]), "=r"(r[1]), "=r"(r[2]), "=r"(r[3]) : "r"(addr));
}
__device__ __forceinline__ void ldsm_x2(uint32_t* r, uint32_t addr) {
    asm volatile("ldmatrix.sync.aligned.m8n8.x2.shared.b16 {%0,%1}, [%2];"
        : "=r"(r[0]), "=r"(r[1]) : "r"(addr));
}
__device__ __forceinline__ void mma_bf16(float* c, const uint32_t* a, const uint32_t* b) {
    asm volatile("mma.sync.aligned.m16n8k16.row.col.f32.bf16.bf16.f32 "
        "{%0,%1,%2,%3}, {%4,%5,%6,%7}, {%8,%9}, {%0,%1,%2,%3};"
        : "+f"(c[0]), "+f"(c[1]), "+f"(c[2]), "+f"(c[3])
        : "r"(a[0]), "r"(a[1]), "r"(a[2]), "r"(a[3]), "r"(b[0]), "r"(b[1]));
}
__device__ __forceinline__ void cp_async16(uint32_t dst, const void* src) {
    asm volatile("cp.async.cg.shared.global [%0], [%1], 16;" :: "r"(dst), "l"(src));
}
#define CP_COMMIT() asm volatile("cp.async.commit_group;" ::: "memory")
#define CP_WAIT2()  asm volatile("cp.async.wait_group 2;" ::: "memory")

// fp32 -> bf16 hi + bf16 lo (exact two-term split)
__device__ __forceinline__ void split1(float v, __nv_bfloat16& h, __nv_bfloat16& l) {
    h = __float2bfloat16_rn(v);
    l = __float2bfloat16_rn(v - __bfloat162float(h));
}

// ---------------------------------------------------------------------------
// Kernel 1: passthrough copy of x into out[0 : XELEMS]
// ---------------------------------------------------------------------------
__global__ void copy_x_kernel(const float4* __restrict__ src, float4* __restrict__ dst) {
    int i = blockIdx.x * blockDim.x + threadIdx.x;
    dst[i] = src[i];
}

// ---------------------------------------------------------------------------
// Kernel 2: ROI max pool -> bf16 hi/lo directly (same bin semantics as the
// verified R8/R11 kernel: XLA reciprocal-multiply, __fmul_rn literal).
// ---------------------------------------------------------------------------
__global__ void roi_pool_kernel(const float* __restrict__ x, const float* __restrict__ boxes) {
    const int k = blockIdx.x;
    const int c = threadIdx.x;
    const float* bx = boxes + k * 5;
    const int b = (int)bx[0];
    const float x1 = rintf(bx[1] * 32.0f);
    const float y1 = rintf(bx[2] * 32.0f);
    const float x2 = rintf(bx[3] * 32.0f);
    const float y2 = rintf(bx[4] * 32.0f);
    const float rw = fmaxf(x2 - x1 + 1.0f, 1.0f);
    const float rh = fmaxf(y2 - y1 + 1.0f, 1.0f);
    const float INV7 = 1.0f / 7.0f;
    const float bsw = __fmul_rn(rw, INV7);
    const float bsh = __fmul_rn(rh, INV7);

    int hs[OS], he[OS], ws[OS], we[OS];
#pragma unroll
    for (int p = 0; p < OS; p++) {
        const float pf = (float)p;
        const float pf1 = (float)(p + 1);
        hs[p] = (int)fminf(fmaxf(floorf(__fmul_rn(pf, bsh)) + y1, 0.0f), 32.0f);
        he[p] = (int)fminf(fmaxf(ceilf(__fmul_rn(pf1, bsh)) + y1, 0.0f), 32.0f);
        ws[p] = (int)fminf(fmaxf(floorf(__fmul_rn(pf, bsw)) + x1, 0.0f), 32.0f);
        we[p] = (int)fminf(fmaxf(ceilf(__fmul_rn(pf1, bsw)) + x1, 0.0f), 32.0f);
    }

    const float* fb = x + (size_t)b * (NT * CH) + c;
    __nv_bfloat16* ph = g_Ahi + (size_t)k * KDIM + (size_t)c * (OS * OS);
    __nv_bfloat16* pl = g_Alo + (size_t)k * KDIM + (size_t)c * (OS * OS);

#pragma unroll
    for (int i = 0; i < OS; i++) {
#pragma unroll
        for (int j = 0; j < OS; j++) {
            float m = -FLT_MAX;
            for (int h = hs[i]; h < he[i]; h++) {
                const float* rowp = fb + (size_t)(h << 5) * CH;
                for (int w = ws[j]; w < we[j]; w++) {
                    m = fmaxf(m, rowp[(size_t)w * CH]);
                }
            }
            m = (m <= -0.5f * FLT_MAX) ? 0.0f : m;
            __nv_bfloat16 hh, ll;
            split1(m, hh, ll);
            ph[i * OS + j] = hh;
            pl[i * OS + j] = ll;
        }
    }
}

// ---------------------------------------------------------------------------
// Kernel 2b: split conv_w fp32 -> bf16 hi/lo (one-shot elementwise)
// ---------------------------------------------------------------------------
__global__ void wsplit_kernel(const float4* __restrict__ w) {
    int i = blockIdx.x * blockDim.x + threadIdx.x;   // over WELEMS/4
    float4 v = w[i];
    __nv_bfloat16 h0, h1, h2, h3, l0, l1, l2, l3;
    split1(v.x, h0, l0); split1(v.y, h1, l1);
    split1(v.z, h2, l2); split1(v.w, h3, l3);
    __nv_bfloat162 hp0; hp0.x = h0; hp0.y = h1;
    __nv_bfloat162 hp1; hp1.x = h2; hp1.y = h3;
    __nv_bfloat162 lp0; lp0.x = l0; lp0.y = l1;
    __nv_bfloat162 lp1; lp1.x = l2; lp1.y = l3;
    uint2 hv, lv;
    hv.x = *reinterpret_cast<uint32_t*>(&hp0); hv.y = *reinterpret_cast<uint32_t*>(&hp1);
    lv.x = *reinterpret_cast<uint32_t*>(&lp0); lv.y = *reinterpret_cast<uint32_t*>(&lp1);
    ((uint2*)g_Bhi)[i] = hv;
    ((uint2*)g_Blo)[i] = lv;
}

// ---------------------------------------------------------------------------
// Kernel 3: bf16-split GEMM via mma.sync, cp.async 3-stage pipeline.
// D = Ahi*Bhi + Ahi*Blo + Alo*Bhi accumulated fp32 (err ~1e-5).
// Grid (2, 4, 16) = 128 CTAs; 256 threads (8 warps, each 64x32); K = 1568
// per CTA in 49 stages of 32.
// ---------------------------------------------------------------------------
__global__ void __launch_bounds__(256) gemm_mma_kernel() {
    extern __shared__ char smem[];
    const uint32_t sb = smem_to_u32(smem);
    const int tid = threadIdx.x;
    const int wid = tid >> 5;
    const int lane = tid & 31;
    const int warp_m = wid & 1;          // 0..1 -> 64-row block
    const int warp_n = wid >> 1;         // 0..3 -> 32-col block

    const int m0 = blockIdx.x * GM;
    const int n0 = blockIdx.y * GN;
    const int kz = blockIdx.z * KCHUNK;

    // cp.async mapping: 2048 16B-ops/stage (4 tiles x 128 rows x 4 segs),
    // 8 per thread: gidx = tid + t*256 -> tile, row, seg
    int cp_row[8], cp_seg[8], cp_tile[8];
#pragma unroll
    for (int t = 0; t < 8; t++) {
        int gidx = tid + t * 256;
        cp_tile[t] = gidx >> 9;          // 0..3
        int rem = gidx & 511;
        cp_row[t] = rem >> 2;            // 0..127
        cp_seg[t] = rem & 3;             // 0..3 (16B = 8 bf16 each)
    }

    // ldmatrix per-lane base offsets (within a tile, before ks offset)
    const uint32_t aoff = (uint32_t)((warp_m * 64 + (lane & 15)) * RS_BYTES + (lane >> 4) * 16);
    const uint32_t boff = (uint32_t)((warp_n * 32 + (lane & 7)) * RS_BYTES + ((lane >> 3) & 1) * 16);

    float acc[4][4][4];
#pragma unroll
    for (int mi = 0; mi < 4; mi++)
#pragma unroll
        for (int ni = 0; ni < 4; ni++)
#pragma unroll
            for (int q = 0; q < 4; q++) acc[mi][ni][q] = 0.0f;

    // stage issue helper (as lambda-free macro-ish code)
    auto issue_stage = [&](int s, int buf) {
        const uint32_t bufb = sb + (uint32_t)buf * STAGE_BYTES;
        const int kofs = kz + s * KST;
#pragma unroll
        for (int t = 0; t < 8; t++) {
            const int row = cp_row[t];
            const int seg = cp_seg[t];
            const uint32_t dst = bufb + (uint32_t)cp_tile[t] * TILE_BYTES
                               + (uint32_t)(row * RS_BYTES + seg * 16);
            const int kk = kofs + seg * 8;
            const __nv_bfloat16* src;
            switch (cp_tile[t]) {
                case 0: src = g_Ahi + (size_t)(m0 + row) * KDIM + kk; break;
                case 1: src = g_Alo + (size_t)(m0 + row) * KDIM + kk; break;
                case 2: src = g_Bhi + (size_t)(n0 + row) * KDIM + kk; break;
                default: src = g_Blo + (size_t)(n0 + row) * KDIM + kk; break;
            }
            cp_async16(dst, src);
        }
    };

    // prologue: stages 0..2
    issue_stage(0, 0); CP_COMMIT();
    issue_stage(1, 1); CP_COMMIT();
    issue_stage(2, 2); CP_COMMIT();

    for (int s = 0; s < NST; s++) {
        CP_WAIT2();
        __syncthreads();
        const uint32_t bufb = sb + (uint32_t)(s % NBUF) * STAGE_BYTES;

#pragma unroll
        for (int ks = 0; ks < 2; ks++) {
            const uint32_t ko = (uint32_t)(ks * 32);
            uint32_t ahi[4][4], alo[4][4], bhi[4][2], blo[4][2];
#pragma unroll
            for (int mi = 0; mi < 4; mi++) {
                ldsm_x4(ahi[mi], bufb + OFF_AHI + aoff + ko + mi * (16 * RS_BYTES));
                ldsm_x4(alo[mi], bufb + OFF_ALO + aoff + ko + mi * (16 * RS_BYTES));
            }
#pragma unroll
            for (int ni = 0; ni < 4; ni++) {
                ldsm_x2(bhi[ni], bufb + OFF_BHI + boff + ko + ni * (8 * RS_BYTES));
                ldsm_x2(blo[ni], bufb + OFF_BLO + boff + ko + ni * (8 * RS_BYTES));
            }
#pragma unroll
            for (int mi = 0; mi < 4; mi++)
#pragma unroll
                for (int ni = 0; ni < 4; ni++) {
                    mma_bf16(acc[mi][ni], ahi[mi], bhi[ni]);
                    mma_bf16(acc[mi][ni], ahi[mi], blo[ni]);
                    mma_bf16(acc[mi][ni], alo[mi], bhi[ni]);
                }
        }

        __syncthreads();   // all warps done reading buf s%3
        if (s + 3 < NST) issue_stage(s + 3, s % NBUF);
        CP_COMMIT();       // unconditional: keeps pending-group count exact
    }

    // epilogue: C fragment layout -> g_partial[z][m][n] (verified in R11)
    float* part = g_partial + (size_t)blockIdx.z * OUTFEATS;
    const int lr = lane >> 2, lc = (lane & 3) * 2;
#pragma unroll
    for (int mi = 0; mi < 4; mi++) {
        const int mrow = m0 + warp_m * 64 + mi * 16 + lr;
#pragma unroll
        for (int ni = 0; ni < 4; ni++) {
            const int ncol = n0 + warp_n * 32 + ni * 8 + lc;
            float* p = part + (size_t)mrow * CH + ncol;
            *(float2*)p = make_float2(acc[mi][ni][0], acc[mi][ni][1]);
            float* p2 = p + 8 * CH;
            *(float2*)p2 = make_float2(acc[mi][ni][2], acc[mi][ni][3]);
        }
    }
}

// ---------------------------------------------------------------------------
// Kernel 4: reduce partials + bias -> out[XELEMS : XELEMS+OUTFEATS]
// ---------------------------------------------------------------------------
__global__ void reduce_kernel(const float* __restrict__ bias, float* __restrict__ out) {
    int idx = blockIdx.x * blockDim.x + threadIdx.x;
    if (idx >= OUTFEATS) return;
    float s = bias[idx & 511];
#pragma unroll
    for (int sp = 0; sp < SPLITS; sp++) s += g_partial[(size_t)sp * OUTFEATS + idx];
    out[XELEMS + idx] = s;
}

// ---------------------------------------------------------------------------
extern "C" void kernel_launch(void* const* d_in, const int* in_sizes, int n_in,
                              void* d_out, int out_size) {
    const float* x      = (const float*)d_in[0];
    const float* boxes  = (const float*)d_in[1];
    const float* conv_w = (const float*)d_in[3];
    const float* conv_b = (const float*)d_in[4];
    float* out = (float*)d_out;

    copy_x_kernel<<<XELEMS / 4 / 256, 256>>>((const float4*)x, (float4*)out);

    roi_pool_kernel<<<NBOX, CH>>>(x, boxes);

    wsplit_kernel<<<WELEMS / 4 / 256, 256>>>((const float4*)conv_w);

    cudaFuncSetAttribute(gemm_mma_kernel,
                         cudaFuncAttributeMaxDynamicSharedMemorySize, GEMM_SMEM);
    {
        dim3 grid(NBOX / GM, CH / GN, SPLITS);
        gemm_mma_kernel<<<grid, 256, GEMM_SMEM>>>();
    }

    reduce_kernel<<<(OUTFEATS + 255) / 256, 256>>>(conv_b, out);
}

// round 13
// speedup vs baseline: 1.3404x; 1.3404x over previous
#include <cuda_runtime.h>
#include <cuda_bf16.h>
#include <cfloat>
#include <cstdint>

// Problem constants
#define BATCH 8
#define NT 1024
#define CH 512
#define NBOX 256
#define OS 7
#define KDIM (OS * OS * CH)      // 25088; K order: c*49 + (i*7+j) (NATIVE conv_w order)
#define XELEMS (BATCH * NT * CH) // 4194304
#define OUTFEATS (NBOX * CH)     // 131072
#define WELEMS (CH * KDIM)       // 12845056

// GEMM config (mma.sync path — base sm_103 target has NO tcgen05)
#define GM 128
#define GN 128
#define SPLITS 32
#define KCHUNK (KDIM / SPLITS)   // 784
#define KST 16
#define NST (KCHUNK / KST)       // 49

// smem per stage: 4 tiles (Ahi,Alo,Bhi,Blo), 128 rows x 16 bf16 (32B data)
// padded to 48B/row: 48*r mod 128 covers all 8 16B bank groups -> ldmatrix
// conflict-free; 48 % 16 == 0 for cp.async.
#define RS_BYTES 48
#define TILE_BYTES (128 * RS_BYTES)      // 6144
#define OFF_AHI 0
#define OFF_ALO (TILE_BYTES)
#define OFF_BHI (2 * TILE_BYTES)
#define OFF_BLO (3 * TILE_BYTES)
#define STAGE_BYTES (4 * TILE_BYTES)     // 24576
#define NBUF 4
#define GEMM_SMEM (NBUF * STAGE_BYTES)   // 98304 -> 2 CTAs/SM

// Device scratch (allocation-free rule: __device__ globals)
__device__ __align__(16) __nv_bfloat16 g_Ahi[NBOX * KDIM];
__device__ __align__(16) __nv_bfloat16 g_Alo[NBOX * KDIM];
__device__ __align__(16) __nv_bfloat16 g_Bhi[WELEMS];
__device__ __align__(16) __nv_bfloat16 g_Blo[WELEMS];
__device__ __align__(16) float g_partial[SPLITS * OUTFEATS];

// ---------------------------------------------------------------------------
// helpers
// ---------------------------------------------------------------------------
__device__ __forceinline__ uint32_t smem_to_u32(const void* p) {
    uint32_t a;
    asm("{ .reg .u64 t; cvta.to.shared.u64 t, %1; cvt.u32.u64 %0, t; }" : "=r"(a) : "l"(p));
    return a;
}
__device__ __forceinline__ void ldsm_x4(uint32_t* r, uint32_t addr) {
    asm volatile("ldmatrix.sync.aligned.m8n8.x4.shared.b16 {%0,%1,%2,%3}, [%4];"
        : "=r"(r[0]), "=r"(r[1]), "=r"(r[2]), "=r"(r[3]) : "r"(addr));
}
__device__ __forceinline__ void ldsm_x2(uint32_t* r, uint32_t addr) {
    asm volatile("ldmatrix.sync.aligned.m8n8.x2.shared.b16 {%0,%1}, [%2];"
        : "=r"(r[0]), "=r"(r[1]) : "r"(addr));
}
__device__ __forceinline__ void mma_bf16(float* c, const uint32_t* a, const uint32_t* b) {
    asm volatile("mma.sync.aligned.m16n8k16.row.col.f32.bf16.bf16.f32 "
        "{%0,%1,%2,%3}, {%4,%5,%6,%7}, {%8,%9}, {%0,%1,%2,%3};"
        : "+f"(c[0]), "+f"(c[1]), "+f"(c[2]), "+f"(c[3])
        : "r"(a[0]), "r"(a[1]), "r"(a[2]), "r"(a[3]), "r"(b[0]), "r"(b[1]));
}
__device__ __forceinline__ void cp_async16(uint32_t dst, const void* src) {
    asm volatile("cp.async.cg.shared.global [%0], [%1], 16;" :: "r"(dst), "l"(src));
}
#define CP_COMMIT() asm volatile("cp.async.commit_group;" ::: "memory")
#define CP_WAIT2()  asm volatile("cp.async.wait_group 2;" ::: "memory")

// fp32 -> bf16 hi + bf16 lo (exact two-term split)
__device__ __forceinline__ void split1(float v, __nv_bfloat16& h, __nv_bfloat16& l) {
    h = __float2bfloat16_rn(v);
    l = __float2bfloat16_rn(v - __bfloat162float(h));
}

// ---------------------------------------------------------------------------
// Kernel 1: passthrough copy of x into out[0 : XELEMS]
// ---------------------------------------------------------------------------
__global__ void copy_x_kernel(const float4* __restrict__ src, float4* __restrict__ dst) {
    int i = blockIdx.x * blockDim.x + threadIdx.x;
    dst[i] = src[i];
}

// ---------------------------------------------------------------------------
// Kernel 2: ROI max pool -> bf16 hi/lo (verified XLA reciprocal-multiply bin
// semantics). Outputs staged in smem, then written with coalesced uint4
// stores (fixes the 16x write-amplification of scattered 2B stores).
// Dynamic smem: 2 * 25088 bf16 = 100352 B.
// ---------------------------------------------------------------------------
__global__ void roi_pool_kernel(const float* __restrict__ x, const float* __restrict__ boxes) {
    extern __shared__ __nv_bfloat16 sp[];          // [0:KDIM) hi, [KDIM:2*KDIM) lo
    __nv_bfloat16* s_hi = sp;
    __nv_bfloat16* s_lo = sp + KDIM;

    const int k = blockIdx.x;
    const int c = threadIdx.x;
    const float* bx = boxes + k * 5;
    const int b = (int)bx[0];
    const float x1 = rintf(bx[1] * 32.0f);
    const float y1 = rintf(bx[2] * 32.0f);
    const float x2 = rintf(bx[3] * 32.0f);
    const float y2 = rintf(bx[4] * 32.0f);
    const float rw = fmaxf(x2 - x1 + 1.0f, 1.0f);
    const float rh = fmaxf(y2 - y1 + 1.0f, 1.0f);
    const float INV7 = 1.0f / 7.0f;
    const float bsw = __fmul_rn(rw, INV7);
    const float bsh = __fmul_rn(rh, INV7);

    int hs[OS], he[OS], ws[OS], we[OS];
#pragma unroll
    for (int p = 0; p < OS; p++) {
        const float pf = (float)p;
        const float pf1 = (float)(p + 1);
        hs[p] = (int)fminf(fmaxf(floorf(__fmul_rn(pf, bsh)) + y1, 0.0f), 32.0f);
        he[p] = (int)fminf(fmaxf(ceilf(__fmul_rn(pf1, bsh)) + y1, 0.0f), 32.0f);
        ws[p] = (int)fminf(fmaxf(floorf(__fmul_rn(pf, bsw)) + x1, 0.0f), 32.0f);
        we[p] = (int)fminf(fmaxf(ceilf(__fmul_rn(pf1, bsw)) + x1, 0.0f), 32.0f);
    }

    const float* fb = x + (size_t)b * (NT * CH) + c;
    __nv_bfloat16* th = s_hi + (size_t)c * (OS * OS);
    __nv_bfloat16* tl = s_lo + (size_t)c * (OS * OS);

#pragma unroll
    for (int i = 0; i < OS; i++) {
#pragma unroll
        for (int j = 0; j < OS; j++) {
            float m = -FLT_MAX;
            for (int h = hs[i]; h < he[i]; h++) {
                const float* rowp = fb + (size_t)(h << 5) * CH;
                for (int w = ws[j]; w < we[j]; w++) {
                    m = fmaxf(m, rowp[(size_t)w * CH]);
                }
            }
            m = (m <= -0.5f * FLT_MAX) ? 0.0f : m;
            __nv_bfloat16 hh, ll;
            split1(m, hh, ll);
            th[i * OS + j] = hh;
            tl[i * OS + j] = ll;
        }
    }
    __syncthreads();

    // coalesced copy-out: KDIM bf16 = 50176 B = 3136 uint4 per array
    const uint4* s4h = (const uint4*)s_hi;
    const uint4* s4l = (const uint4*)s_lo;
    uint4* dh = (uint4*)(g_Ahi + (size_t)k * KDIM);
    uint4* dl = (uint4*)(g_Alo + (size_t)k * KDIM);
    for (int i = c; i < KDIM / 8; i += CH) {
        dh[i] = s4h[i];
        dl[i] = s4l[i];
    }
}

// ---------------------------------------------------------------------------
// Kernel 2b: split conv_w fp32 -> bf16 hi/lo (one-shot, fully coalesced)
// ---------------------------------------------------------------------------
__global__ void wsplit_kernel(const float4* __restrict__ w) {
    int i = blockIdx.x * blockDim.x + threadIdx.x;   // over WELEMS/4
    float4 v = w[i];
    __nv_bfloat16 h0, h1, h2, h3, l0, l1, l2, l3;
    split1(v.x, h0, l0); split1(v.y, h1, l1);
    split1(v.z, h2, l2); split1(v.w, h3, l3);
    __nv_bfloat162 hp0; hp0.x = h0; hp0.y = h1;
    __nv_bfloat162 hp1; hp1.x = h2; hp1.y = h3;
    __nv_bfloat162 lp0; lp0.x = l0; lp0.y = l1;
    __nv_bfloat162 lp1; lp1.x = l2; lp1.y = l3;
    uint2 hv, lv;
    hv.x = *reinterpret_cast<uint32_t*>(&hp0); hv.y = *reinterpret_cast<uint32_t*>(&hp1);
    lv.x = *reinterpret_cast<uint32_t*>(&lp0); lv.y = *reinterpret_cast<uint32_t*>(&lp1);
    ((uint2*)g_Bhi)[i] = hv;
    ((uint2*)g_Blo)[i] = lv;
}

// ---------------------------------------------------------------------------
// Kernel 3: bf16-split GEMM via mma.sync, cp.async 4-buffer pipeline.
// D = Ahi*Bhi + Ahi*Blo + Alo*Bhi accumulated fp32 (err ~1e-5).
// Grid (2, 4, 32) = 256 CTAs; 2 CTAs/SM (96KB smem); 8 warps x 64x32;
// K = 784 per CTA in 49 stages of 16.
// ---------------------------------------------------------------------------
__global__ void __launch_bounds__(256, 2) gemm_mma_kernel() {
    extern __shared__ char smem[];
    const uint32_t sb = smem_to_u32(smem);
    const int tid = threadIdx.x;
    const int wid = tid >> 5;
    const int lane = tid & 31;
    const int warp_m = wid & 1;          // 0..1 -> 64-row block
    const int warp_n = wid >> 1;         // 0..3 -> 32-col block

    const int m0 = blockIdx.x * GM;
    const int n0 = blockIdx.y * GN;
    const int kz = blockIdx.z * KCHUNK;

    // cp.async: 1024 16B-ops/stage (4 tiles x 128 rows x 2 segs); 4/thread
    int cp_row[4], cp_seg[4], cp_tile[4];
#pragma unroll
    for (int t = 0; t < 4; t++) {
        int gidx = tid + t * 256;        // 0..1023
        cp_tile[t] = gidx >> 8;          // 0..3
        int rem = gidx & 255;
        cp_row[t] = rem >> 1;            // 0..127
        cp_seg[t] = rem & 1;             // 0..1 (16B = 8 bf16 each)
    }

    const uint32_t aoff = (uint32_t)((warp_m * 64 + (lane & 15)) * RS_BYTES + (lane >> 4) * 16);
    const uint32_t boff = (uint32_t)((warp_n * 32 + (lane & 7)) * RS_BYTES + ((lane >> 3) & 1) * 16);

    float acc[4][4][4];
#pragma unroll
    for (int mi = 0; mi < 4; mi++)
#pragma unroll
        for (int ni = 0; ni < 4; ni++)
#pragma unroll
            for (int q = 0; q < 4; q++) acc[mi][ni][q] = 0.0f;

    auto issue_stage = [&](int s, int buf) {
        const uint32_t bufb = sb + (uint32_t)buf * STAGE_BYTES;
        const int kofs = kz + s * KST;
#pragma unroll
        for (int t = 0; t < 4; t++) {
            const int row = cp_row[t];
            const int seg = cp_seg[t];
            const uint32_t dst = bufb + (uint32_t)cp_tile[t] * TILE_BYTES
                               + (uint32_t)(row * RS_BYTES + seg * 16);
            const int kk = kofs + seg * 8;
            const __nv_bfloat16* src;
            switch (cp_tile[t]) {
                case 0: src = g_Ahi + (size_t)(m0 + row) * KDIM + kk; break;
                case 1: src = g_Alo + (size_t)(m0 + row) * KDIM + kk; break;
                case 2: src = g_Bhi + (size_t)(n0 + row) * KDIM + kk; break;
                default: src = g_Blo + (size_t)(n0 + row) * KDIM + kk; break;
            }
            cp_async16(dst, src);
        }
    };

    issue_stage(0, 0); CP_COMMIT();
    issue_stage(1, 1); CP_COMMIT();
    issue_stage(2, 2); CP_COMMIT();

    for (int s = 0; s < NST; s++) {
        CP_WAIT2();
        __syncthreads();
        const uint32_t bufb = sb + (uint32_t)(s % NBUF) * STAGE_BYTES;

        uint32_t ahi[4][4], alo[4][4], bhi[4][2], blo[4][2];
#pragma unroll
        for (int mi = 0; mi < 4; mi++) {
            ldsm_x4(ahi[mi], bufb + OFF_AHI + aoff + mi * (16 * RS_BYTES));
            ldsm_x4(alo[mi], bufb + OFF_ALO + aoff + mi * (16 * RS_BYTES));
        }
#pragma unroll
        for (int ni = 0; ni < 4; ni++) {
            ldsm_x2(bhi[ni], bufb + OFF_BHI + boff + ni * (8 * RS_BYTES));
            ldsm_x2(blo[ni], bufb + OFF_BLO + boff + ni * (8 * RS_BYTES));
        }
#pragma unroll
        for (int mi = 0; mi < 4; mi++)
#pragma unroll
            for (int ni = 0; ni < 4; ni++) {
                mma_bf16(acc[mi][ni], ahi[mi], bhi[ni]);
                mma_bf16(acc[mi][ni], ahi[mi], blo[ni]);
                mma_bf16(acc[mi][ni], alo[mi], bhi[ni]);
            }

        __syncthreads();   // all warps done reading buf s%4
        if (s + 3 < NST) issue_stage(s + 3, (s + 3) % NBUF);
        CP_COMMIT();       // unconditional: keeps pending-group count exact
    }

    // epilogue: C fragment layout -> g_partial[z][m][n] (verified R11/R12)
    float* part = g_partial + (size_t)blockIdx.z * OUTFEATS;
    const int lr = lane >> 2, lc = (lane & 3) * 2;
#pragma unroll
    for (int mi = 0; mi < 4; mi++) {
        const int mrow = m0 + warp_m * 64 + mi * 16 + lr;
#pragma unroll
        for (int ni = 0; ni < 4; ni++) {
            const int ncol = n0 + warp_n * 32 + ni * 8 + lc;
            float* p = part + (size_t)mrow * CH + ncol;
            *(float2*)p = make_float2(acc[mi][ni][0], acc[mi][ni][1]);
            float* p2 = p + 8 * CH;
            *(float2*)p2 = make_float2(acc[mi][ni][2], acc[mi][ni][3]);
        }
    }
}

// ---------------------------------------------------------------------------
// Kernel 4: reduce partials + bias -> out[XELEMS : XELEMS+OUTFEATS]
// ---------------------------------------------------------------------------
__global__ void reduce_kernel(const float* __restrict__ bias, float* __restrict__ out) {
    int idx = blockIdx.x * blockDim.x + threadIdx.x;
    if (idx >= OUTFEATS) return;
    float s = bias[idx & 511];
#pragma unroll
    for (int sp = 0; sp < SPLITS; sp++) s += g_partial[(size_t)sp * OUTFEATS + idx];
    out[XELEMS + idx] = s;
}

// ---------------------------------------------------------------------------
extern "C" void kernel_launch(void* const* d_in, const int* in_sizes, int n_in,
                              void* d_out, int out_size) {
    const float* x      = (const float*)d_in[0];
    const float* boxes  = (const float*)d_in[1];
    const float* conv_w = (const float*)d_in[3];
    const float* conv_b = (const float*)d_in[4];
    float* out = (float*)d_out;

    copy_x_kernel<<<XELEMS / 4 / 256, 256>>>((const float4*)x, (float4*)out);

    const int pool_smem = 2 * KDIM * (int)sizeof(__nv_bfloat16);   // 100352
    cudaFuncSetAttribute(roi_pool_kernel,
                         cudaFuncAttributeMaxDynamicSharedMemorySize, pool_smem);
    roi_pool_kernel<<<NBOX, CH, pool_smem>>>(x, boxes);

    wsplit_kernel<<<WELEMS / 4 / 256, 256>>>((const float4*)conv_w);

    cudaFuncSetAttribute(gemm_mma_kernel,
                         cudaFuncAttributeMaxDynamicSharedMemorySize, GEMM_SMEM);
    {
        dim3 grid(NBOX / GM, CH / GN, SPLITS);
        gemm_mma_kernel<<<grid, 256, GEMM_SMEM>>>();
    }

    reduce_kernel<<<(OUTFEATS + 255) / 256, 256>>>(conv_b, out);
}

// round 16
// speedup vs baseline: 2.0365x; 1.5193x over previous
#include <cuda_runtime.h>
#include <cuda_fp16.h>
#include <cfloat>
#include <cstdint>

// Problem constants
#define BATCH 8
#define NT 1024
#define CH 512
#define NBOX 256
#define OS 7
#define KDIM (OS * OS * CH)      // 25088; K order: c*49 + (i*7+j) (NATIVE conv_w order)
#define XELEMS (BATCH * NT * CH) // 4194304
#define OUTFEATS (NBOX * CH)     // 131072
#define WELEMS (CH * KDIM)       // 12845056

// GEMM config: single-pass fp16 mma.sync (legacy HMMA roofline-bound, so
// minimize HMMA count: 1 pass instead of 3)
#define GM 128
#define GN 128
#define SPLITS 16
#define KCHUNK (KDIM / SPLITS)   // 1568
#define KST 32
#define NST (KCHUNK / KST)       // 49

// smem per stage: 2 tiles (A, B), 128 rows x 32 fp16 (64B data) padded to
// 80B/row: 80*r mod 128 -> offsets {0,80,32,112,64,16,96,48}: all 8 16B bank
// groups distinct -> ldmatrix conflict-free; 80 % 16 == 0 for cp.async.
#define RS_BYTES 80
#define TILE_BYTES (128 * RS_BYTES)      // 10240
#define OFF_A 0
#define OFF_B (TILE_BYTES)
#define STAGE_BYTES (2 * TILE_BYTES)     // 20480
#define NBUF 4
#define GEMM_SMEM (NBUF * STAGE_BYTES)   // 81920

// Device scratch (allocation-free rule: __device__ globals)
__device__ __align__(16) __half g_A[NBOX * KDIM];
__device__ __align__(16) __half g_B[WELEMS];
__device__ __align__(16) float g_partial[SPLITS * OUTFEATS];

// ---------------------------------------------------------------------------
// helpers
// ---------------------------------------------------------------------------
__device__ __forceinline__ uint32_t smem_to_u32(const void* p) {
    uint32_t a;
    asm("{ .reg .u64 t; cvta.to.shared.u64 t, %1; cvt.u32.u64 %0, t; }" : "=r"(a) : "l"(p));
    return a;
}
__device__ __forceinline__ void ldsm_x4(uint32_t* r, uint32_t addr) {
    asm volatile("ldmatrix.sync.aligned.m8n8.x4.shared.b16 {%0,%1,%2,%3}, [%4];"
        : "=r"(r[0]), "=r"(r[1]), "=r"(r[2]), "=r"(r[3]) : "r"(addr));
}
__device__ __forceinline__ void ldsm_x2(uint32_t* r, uint32_t addr) {
    asm volatile("ldmatrix.sync.aligned.m8n8.x2.shared.b16 {%0,%1}, [%2];"
        : "=r"(r[0]), "=r"(r[1]) : "r"(addr));
}
__device__ __forceinline__ void mma_f16(float* c, const uint32_t* a, const uint32_t* b) {
    asm volatile("mma.sync.aligned.m16n8k16.row.col.f32.f16.f16.f32 "
        "{%0,%1,%2,%3}, {%4,%5,%6,%7}, {%8,%9}, {%0,%1,%2,%3};"
        : "+f"(c[0]), "+f"(c[1]), "+f"(c[2]), "+f"(c[3])
        : "r"(a[0]), "r"(a[1]), "r"(a[2]), "r"(a[3]), "r"(b[0]), "r"(b[1]));
}
__device__ __forceinline__ void cp_async16(uint32_t dst, const void* src) {
    asm volatile("cp.async.cg.shared.global [%0], [%1], 16;" :: "r"(dst), "l"(src));
}
#define CP_COMMIT() asm volatile("cp.async.commit_group;" ::: "memory")
#define CP_WAIT2()  asm volatile("cp.async.wait_group 2;" ::: "memory")

// ---------------------------------------------------------------------------
// Kernel 1: passthrough copy of x into out[0 : XELEMS]
// ---------------------------------------------------------------------------
__global__ void copy_x_kernel(const float4* __restrict__ src, float4* __restrict__ dst) {
    int i = blockIdx.x * blockDim.x + threadIdx.x;
    dst[i] = src[i];
}

// ---------------------------------------------------------------------------
// Kernel 2: ROI max pool -> fp16 (verified XLA reciprocal-multiply bin
// semantics). Output staged in smem, coalesced uint4 copy-out.
// Dynamic smem: KDIM fp16 = 50176 B.
// ---------------------------------------------------------------------------
__global__ void roi_pool_kernel(const float* __restrict__ x, const float* __restrict__ boxes) {
    extern __shared__ __half sp[];

    const int k = blockIdx.x;
    const int c = threadIdx.x;
    const float* bx = boxes + k * 5;
    const int b = (int)bx[0];
    const float x1 = rintf(bx[1] * 32.0f);
    const float y1 = rintf(bx[2] * 32.0f);
    const float x2 = rintf(bx[3] * 32.0f);
    const float y2 = rintf(bx[4] * 32.0f);
    const float rw = fmaxf(x2 - x1 + 1.0f, 1.0f);
    const float rh = fmaxf(y2 - y1 + 1.0f, 1.0f);
    const float INV7 = 1.0f / 7.0f;
    const float bsw = __fmul_rn(rw, INV7);
    const float bsh = __fmul_rn(rh, INV7);

    int hs[OS], he[OS], ws[OS], we[OS];
#pragma unroll
    for (int p = 0; p < OS; p++) {
        const float pf = (float)p;
        const float pf1 = (float)(p + 1);
        hs[p] = (int)fminf(fmaxf(floorf(__fmul_rn(pf, bsh)) + y1, 0.0f), 32.0f);
        he[p] = (int)fminf(fmaxf(ceilf(__fmul_rn(pf1, bsh)) + y1, 0.0f), 32.0f);
        ws[p] = (int)fminf(fmaxf(floorf(__fmul_rn(pf, bsw)) + x1, 0.0f), 32.0f);
        we[p] = (int)fminf(fmaxf(ceilf(__fmul_rn(pf1, bsw)) + x1, 0.0f), 32.0f);
    }

    const float* fb = x + (size_t)b * (NT * CH) + c;
    __half* th = sp + (size_t)c * (OS * OS);

#pragma unroll
    for (int i = 0; i < OS; i++) {
#pragma unroll
        for (int j = 0; j < OS; j++) {
            float m = -FLT_MAX;
            for (int h = hs[i]; h < he[i]; h++) {
                const float* rowp = fb + (size_t)(h << 5) * CH;
                for (int w = ws[j]; w < we[j]; w++) {
                    m = fmaxf(m, rowp[(size_t)w * CH]);
                }
            }
            m = (m <= -0.5f * FLT_MAX) ? 0.0f : m;
            th[i * OS + j] = __float2half_rn(m);
        }
    }
    __syncthreads();

    // coalesced copy-out: KDIM fp16 = 50176 B = 3136 uint4
    const uint4* s4 = (const uint4*)sp;
    uint4* dst = (uint4*)(g_A + (size_t)k * KDIM);
    for (int i = c; i < KDIM / 8; i += CH) dst[i] = s4[i];
}

// ---------------------------------------------------------------------------
// Kernel 2b: convert conv_w fp32 -> fp16 (one-shot, coalesced; 8 elems/thread)
// ---------------------------------------------------------------------------
__global__ void wconv_kernel(const float4* __restrict__ w) {
    int i = blockIdx.x * blockDim.x + threadIdx.x;   // over WELEMS/8
    float4 v0 = w[2 * i];
    float4 v1 = w[2 * i + 1];
    __half2 h0 = __floats2half2_rn(v0.x, v0.y);
    __half2 h1 = __floats2half2_rn(v0.z, v0.w);
    __half2 h2 = __floats2half2_rn(v1.x, v1.y);
    __half2 h3 = __floats2half2_rn(v1.z, v1.w);
    uint4 out;
    out.x = *reinterpret_cast<uint32_t*>(&h0);
    out.y = *reinterpret_cast<uint32_t*>(&h1);
    out.z = *reinterpret_cast<uint32_t*>(&h2);
    out.w = *reinterpret_cast<uint32_t*>(&h3);
    ((uint4*)g_B)[i] = out;
}

// ---------------------------------------------------------------------------
// Kernel 3: single-pass fp16 GEMM via mma.sync (f32 accum).
// D[m,n] = sum_t A[m,t]*B[n,t]; statistical rel_err ~2.5e-4 << 1e-3.
// Grid (2, 4, 16) = 128 CTAs; 8 warps x 64x32; K = 1568/CTA in 49 stages
// of 32; cp.async 4-buffer pipeline.
// ---------------------------------------------------------------------------
__global__ void __launch_bounds__(256, 2) gemm_mma_kernel() {
    extern __shared__ char smem[];
    const uint32_t sb = smem_to_u32(smem);
    const int tid = threadIdx.x;
    const int wid = tid >> 5;
    const int lane = tid & 31;
    const int warp_m = wid & 1;          // 0..1 -> 64-row block
    const int warp_n = wid >> 1;         // 0..3 -> 32-col block

    const int m0 = blockIdx.x * GM;
    const int n0 = blockIdx.y * GN;
    const int kz = blockIdx.z * KCHUNK;

    // cp.async: 1024 16B-ops/stage (2 tiles x 128 rows x 4 segs); 4/thread
    int cp_row[4], cp_seg[4], cp_tile[4];
#pragma unroll
    for (int t = 0; t < 4; t++) {
        int gidx = tid + t * 256;        // 0..1023
        cp_tile[t] = gidx >> 9;          // 0..1
        int rem = gidx & 511;
        cp_row[t] = rem >> 2;            // 0..127
        cp_seg[t] = rem & 3;             // 0..3 (16B = 8 fp16 each)
    }

    const uint32_t aoff = (uint32_t)((warp_m * 64 + (lane & 15)) * RS_BYTES + (lane >> 4) * 16);
    const uint32_t boff = (uint32_t)((warp_n * 32 + (lane & 7)) * RS_BYTES + ((lane >> 3) & 1) * 16);

    float acc[4][4][4];
#pragma unroll
    for (int mi = 0; mi < 4; mi++)
#pragma unroll
        for (int ni = 0; ni < 4; ni++)
#pragma unroll
            for (int q = 0; q < 4; q++) acc[mi][ni][q] = 0.0f;

    auto issue_stage = [&](int s, int buf) {
        const uint32_t bufb = sb + (uint32_t)buf * STAGE_BYTES;
        const int kofs = kz + s * KST;
#pragma unroll
        for (int t = 0; t < 4; t++) {
            const int row = cp_row[t];
            const int seg = cp_seg[t];
            const uint32_t dst = bufb + (uint32_t)cp_tile[t] * TILE_BYTES
                               + (uint32_t)(row * RS_BYTES + seg * 16);
            const int kk = kofs + seg * 8;
            const __half* src = cp_tile[t]
                ? g_B + (size_t)(n0 + row) * KDIM + kk
                : g_A + (size_t)(m0 + row) * KDIM + kk;
            cp_async16(dst, src);
        }
    };

    issue_stage(0, 0); CP_COMMIT();
    issue_stage(1, 1); CP_COMMIT();
    issue_stage(2, 2); CP_COMMIT();

    for (int s = 0; s < NST; s++) {
        CP_WAIT2();
        __syncthreads();
        const uint32_t bufb = sb + (uint32_t)(s % NBUF) * STAGE_BYTES;

#pragma unroll
        for (int kh = 0; kh < 2; kh++) {
            const uint32_t ko = (uint32_t)(kh * 32);   // 16 fp16 = 32B per k-half
            uint32_t af[4][4], bf[4][2];
#pragma unroll
            for (int mi = 0; mi < 4; mi++)
                ldsm_x4(af[mi], bufb + OFF_A + aoff + ko + mi * (16 * RS_BYTES));
#pragma unroll
            for (int ni = 0; ni < 4; ni++)
                ldsm_x2(bf[ni], bufb + OFF_B + boff + ko + ni * (8 * RS_BYTES));
#pragma unroll
            for (int mi = 0; mi < 4; mi++)
#pragma unroll
                for (int ni = 0; ni < 4; ni++)
                    mma_f16(acc[mi][ni], af[mi], bf[ni]);
        }

        __syncthreads();   // all warps done reading buf s%4
        if (s + 3 < NST) issue_stage(s + 3, (s + 3) % NBUF);
        CP_COMMIT();       // unconditional: keeps pending-group count exact
    }

    // epilogue: C fragment layout -> g_partial[z][m][n] (verified R11-R13)
    float* part = g_partial + (size_t)blockIdx.z * OUTFEATS;
    const int lr = lane >> 2, lc = (lane & 3) * 2;
#pragma unroll
    for (int mi = 0; mi < 4; mi++) {
        const int mrow = m0 + warp_m * 64 + mi * 16 + lr;
#pragma unroll
        for (int ni = 0; ni < 4; ni++) {
            const int ncol = n0 + warp_n * 32 + ni * 8 + lc;
            float* p = part + (size_t)mrow * CH + ncol;
            *(float2*)p = make_float2(acc[mi][ni][0], acc[mi][ni][1]);
            float* p2 = p + 8 * CH;
            *(float2*)p2 = make_float2(acc[mi][ni][2], acc[mi][ni][3]);
        }
    }
}

// ---------------------------------------------------------------------------
// Kernel 4: reduce partials + bias -> out[XELEMS : XELEMS+OUTFEATS]
// ---------------------------------------------------------------------------
__global__ void reduce_kernel(const float* __restrict__ bias, float* __restrict__ out) {
    int idx = blockIdx.x * blockDim.x + threadIdx.x;
    if (idx >= OUTFEATS) return;
    float s = bias[idx & 511];
#pragma unroll
    for (int sp = 0; sp < SPLITS; sp++) s += g_partial[(size_t)sp * OUTFEATS + idx];
    out[XELEMS + idx] = s;
}

// ---------------------------------------------------------------------------
extern "C" void kernel_launch(void* const* d_in, const int* in_sizes, int n_in,
                              void* d_out, int out_size) {
    const float* x      = (const float*)d_in[0];
    const float* boxes  = (const float*)d_in[1];
    const float* conv_w = (const float*)d_in[3];
    const float* conv_b = (const float*)d_in[4];
    float* out = (float*)d_out;

    copy_x_kernel<<<XELEMS / 4 / 256, 256>>>((const float4*)x, (float4*)out);

    const int pool_smem = KDIM * (int)sizeof(__half);   // 50176
    cudaFuncSetAttribute(roi_pool_kernel,
                         cudaFuncAttributeMaxDynamicSharedMemorySize, pool_smem);
    roi_pool_kernel<<<NBOX, CH, pool_smem>>>(x, boxes);

    wconv_kernel<<<WELEMS / 8 / 256, 256>>>((const float4*)conv_w);

    cudaFuncSetAttribute(gemm_mma_kernel,
                         cudaFuncAttributeMaxDynamicSharedMemorySize, GEMM_SMEM);
    {
        dim3 grid(NBOX / GM, CH / GN, SPLITS);
        gemm_mma_kernel<<<grid, 256, GEMM_SMEM>>>();
    }

    reduce_kernel<<<(OUTFEATS + 255) / 256, 256>>>(conv_b, out);
}